// round 5
// baseline (speedup 1.0000x reference)
#include <cuda_runtime.h>
#include <cstdint>

#define BB 128
#define TT 784
#define HH 256
#define LL 20
#define CC 10

// Scratch (device globals: allocation-free per harness rules)
__device__ float g_xp[(size_t)BB * TT * HH];   // per-layer input projection [B*T, H]
__device__ float g_h [(size_t)BB * TT * HH];   // per-layer hidden output   [B*T, H]

// ---------------------------------------------------------------------------
// helpers
// ---------------------------------------------------------------------------
__device__ __forceinline__ uint32_t smem_u32(const void* p) {
    uint32_t a;
    asm("{ .reg .u64 t; cvta.to.shared.u64 t, %1; cvt.u32.u64 %0, t; }"
        : "=r"(a) : "l"(p));
    return a;
}

// packed fp32x2 fma: c = a*b + c   (Blackwell f32x2 pipe, PTX-only)
__device__ __forceinline__ void ffma2(float2& c, float2 a, float2 b) {
    union U { float2 f; unsigned long long u; };
    U A, Bv, C;
    A.f = a; Bv.f = b; C.f = c;
    asm("fma.rn.f32x2 %0, %1, %2, %3;"
        : "=l"(C.u) : "l"(A.u), "l"(Bv.u), "l"(C.u));
    c = C.f;
}

// cluster-scope parity wait on a local mbarrier (acquire: makes peer DSMEM
// stores visible)
__device__ __forceinline__ void mbar_wait_cluster(uint32_t mbar, uint32_t parity) {
    uint32_t done;
    asm volatile(
        "{\n\t.reg .pred p;\n\t"
        "mbarrier.try_wait.parity.acquire.cluster.shared::cta.b64 p, [%1], %2;\n\t"
        "selp.b32 %0, 1, 0, p;\n\t}"
        : "=r"(done) : "r"(mbar), "r"(parity) : "memory");
    while (!done) {
        asm volatile(
            "{\n\t.reg .pred p;\n\t"
            "mbarrier.try_wait.parity.acquire.cluster.shared::cta.b64 p, [%1], %2, 0x989680;\n\t"
            "selp.b32 %0, 1, 0, p;\n\t}"
            : "=r"(done) : "r"(mbar), "r"(parity) : "memory");
    }
}

// release.cluster arrive on a REMOTE (peer-CTA) mbarrier (addr pre-mapa'd)
__device__ __forceinline__ void mbar_arrive_remote(uint32_t remote_mbar) {
    asm volatile("mbarrier.arrive.release.cluster.shared::cluster.b64 _, [%0];"
                 :: "r"(remote_mbar) : "memory");
}

// ---------------------------------------------------------------------------
// Layer-0 projection: xp[b,t,h] = x[b,t,0]*W_ih0[h,0] + b_ih0[h]  (I==1)
// ---------------------------------------------------------------------------
__global__ void proj0_kernel(const float* __restrict__ x,
                             const float* __restrict__ W0,
                             const float* __restrict__ b0) {
    int row = blockIdx.x;
    int j   = threadIdx.x;
    g_xp[(size_t)row * HH + j] = x[row] * W0[j] + b0[j];
}

// ---------------------------------------------------------------------------
// Projection GEMM (unchanged: measured 84% of fp32 FFMA peak)
//   g_xp[row, n] = sum_k g_h[row, k] * W_ih[l][n, k] + b_ih[l][n]
// ---------------------------------------------------------------------------
__global__ __launch_bounds__(256) void proj_kernel(const float* __restrict__ Wih,
                                                   const float* __restrict__ bih,
                                                   int l) {
    const float* A    = g_h;
    const float* Bw   = Wih + (size_t)l * HH * HH;
    const float* bias = bih + (size_t)l * HH;
    float*       Cout = g_xp;

    int tid = threadIdx.x;
    int tx  = tid & 15;
    int ty  = tid >> 4;
    int r0  = blockIdx.x * 128;
    int c0  = blockIdx.y * 128;

    __shared__ float Ash[128][17];
    __shared__ float Bsh[16][132];

    float acc[8][8];
#pragma unroll
    for (int i = 0; i < 8; i++)
#pragma unroll
        for (int j = 0; j < 8; j++) acc[i][j] = 0.0f;

    for (int kt = 0; kt < HH; kt += 16) {
#pragma unroll
        for (int p = 0; p < 8; p++) {
            int f = tid + p * 256;
            int m = f >> 4;
            int k = f & 15;
            Ash[m][k] = A[(size_t)(r0 + m) * HH + kt + k];
        }
#pragma unroll
        for (int p = 0; p < 8; p++) {
            int f = tid + p * 256;
            int n = f >> 4;
            int k = f & 15;
            Bsh[k][n] = Bw[(size_t)(c0 + n) * HH + kt + k];
        }
        __syncthreads();
#pragma unroll
        for (int kk = 0; kk < 16; kk++) {
            float a[8], b[8];
#pragma unroll
            for (int i = 0; i < 8; i++) a[i] = Ash[ty * 8 + i][kk];
            float4 bv0 = *(const float4*)&Bsh[kk][tx * 8];
            float4 bv1 = *(const float4*)&Bsh[kk][tx * 8 + 4];
            b[0] = bv0.x; b[1] = bv0.y; b[2] = bv0.z; b[3] = bv0.w;
            b[4] = bv1.x; b[5] = bv1.y; b[6] = bv1.z; b[7] = bv1.w;
#pragma unroll
            for (int i = 0; i < 8; i++)
#pragma unroll
                for (int j = 0; j < 8; j++)
                    acc[i][j] = fmaf(a[i], b[j], acc[i][j]);
        }
        __syncthreads();
    }

    float bj[8];
#pragma unroll
    for (int j = 0; j < 8; j++) bj[j] = bias[c0 + tx * 8 + j];
#pragma unroll
    for (int i = 0; i < 8; i++) {
        int row = r0 + ty * 8 + i;
#pragma unroll
        for (int j = 0; j < 8; j++)
            Cout[(size_t)row * HH + c0 + tx * 8 + j] = acc[i][j] + bj[j];
    }
}

// ---------------------------------------------------------------------------
// Recurrent scan, cluster-of-2, W in registers, mbarrier handshake sync.
//
// Grid 128 CTAs (64 clusters of 2), 256 threads. Cluster = 2 batch samples.
// CTA rank r computes output cols [r*128, +128).
// Thread (j = tid>>1, kh = tid&1): W row jg = r*128+j, two 64-wide k-quarters
// (own + peer). Double-buffered h in smem; per step:
//   phase1 FMA (own quarter, local data)
//   wait full[cur]  (peer's DSMEM stores of buffer cur visible; overlapped)
//   phase2 FMA (peer quarter)
//   wait rdone[nxt] (peer finished reading buffer nxt; pre-satisfied)
//   epilogue: relu, local stores; DSMEM stores + remote arrives SKIPPED on
//   the last step (nothing consumes them; in-flight remote traffic at CTA
//   exit was the R3/R4 launch-failure cause). Final cluster barrier drains
//   everything before exit.
// ---------------------------------------------------------------------------
#define QPAD 68        // floats per 64-col quarter (16B-aligned, bank-shifted)
#define HROW (4*QPAD)  // floats per buffer row (272)

__global__ __launch_bounds__(256, 1) __cluster_dims__(2, 1, 1)
void scan_kernel(const float* __restrict__ Whh,
                 const float* __restrict__ bhh,
                 int l) {
    __shared__ __align__(16) float sm_h0[2][HROW];  // sample 0, double-buffered
    __shared__ __align__(16) float sm_h1[2][HROW];  // sample 1
    __shared__ __align__(8)  unsigned long long mb[4];  // full0,full1,rdone0,rdone1

    const int tid  = threadIdx.x;
    const int j    = tid >> 1;          // 0..127 local output col
    const int kh   = tid & 1;           // quarter selector within each half
    const int rank = blockIdx.x & 1;
    const int peer = rank ^ 1;
    const int pair = blockIdx.x >> 1;   // 0..63
    const int b0   = pair * 2;
    const int b1   = b0 + 1;
    const int jg   = rank * 128 + j;    // global output col

    // ---- load W quarters into registers (once per layer) ----
    float4 wown[16], wpeer[16];
    {
        const float* Wrow = Whh + ((size_t)l * HH + jg) * HH;
        const float4* po = (const float4*)(Wrow + rank * 128 + kh * 64);
        const float4* pp = (const float4*)(Wrow + peer * 128 + kh * 64);
#pragma unroll
        for (int i = 0; i < 16; i++) wown[i]  = po[i];
#pragma unroll
        for (int i = 0; i < 16; i++) wpeer[i] = pp[i];
    }

    // ---- zero h state ----
    for (int i = tid; i < HROW; i += 256) {
        sm_h0[0][i] = 0.0f; sm_h0[1][i] = 0.0f;
        sm_h1[0][i] = 0.0f; sm_h1[1][i] = 0.0f;
    }

    // ---- mbarrier setup ----
    uint32_t mb_base = smem_u32(&mb[0]);
    const uint32_t mfull0  = mb_base + 0;
    const uint32_t mfull1  = mb_base + 8;
    const uint32_t mrdone0 = mb_base + 16;
    const uint32_t mrdone1 = mb_base + 24;
    __syncthreads();   // zero-init + W loads before barrier init/pre-arm
    if (tid == 0) {
#pragma unroll
        for (int i = 0; i < 4; i++)
            asm volatile("mbarrier.init.shared.b64 [%0], %1;"
                         :: "r"(mb_base + i * 8), "r"(1) : "memory");
        // pre-arm: buffer 0 is valid (zeros, local), buffer 1 never read yet
        asm volatile("mbarrier.arrive.shared.b64 _, [%0];" :: "r"(mfull0)  : "memory");
        asm volatile("mbarrier.arrive.shared.b64 _, [%0];" :: "r"(mrdone1) : "memory");
    }
    __syncthreads();
    // both CTAs' smem (buffers + initialized barriers) valid before any
    // remote arrive / DSMEM store
    asm volatile("barrier.cluster.arrive.aligned;" ::: "memory");
    asm volatile("barrier.cluster.wait.aligned;"   ::: "memory");

    // remote (peer CTA) addresses
    uint32_t loc0 = smem_u32(&sm_h0[0][0]);
    uint32_t loc1 = smem_u32(&sm_h1[0][0]);
    uint32_t rem0, rem1, rmb;
    asm("mapa.shared::cluster.u32 %0, %1, %2;" : "=r"(rem0) : "r"(loc0), "r"(peer));
    asm("mapa.shared::cluster.u32 %0, %1, %2;" : "=r"(rem1) : "r"(loc1), "r"(peer));
    asm("mapa.shared::cluster.u32 %0, %1, %2;" : "=r"(rmb)  : "r"(mb_base), "r"(peer));

    // smem read bases: quarter q of global col c lives at q*QPAD + (c&63)
    const float* own0 = &sm_h0[0][(rank * 2 + kh) * QPAD];
    const float* own1 = &sm_h1[0][(rank * 2 + kh) * QPAD];
    const float* pr0  = &sm_h0[0][(peer * 2 + kh) * QPAD];
    const float* pr1  = &sm_h1[0][(peer * 2 + kh) * QPAD];

    // even-lane finalize state
    float bj = 0.0f;
    const float* xp0 = g_xp + (size_t)b0 * TT * HH + jg;
    const float* xp1 = g_xp + (size_t)b1 * TT * HH + jg;
    float*       ho0 = g_h  + (size_t)b0 * TT * HH + jg;
    float*       ho1 = g_h  + (size_t)b1 * TT * HH + jg;
    if (kh == 0) bj = bhh[l * HH + jg];

    // write slot for col jg: quarter = rank*2 + (j>>6)
    const int slot = (rank * 2 + (j >> 6)) * QPAD + (j & 63);

    // per-barrier parity bits (toggle after each consumption)
    int phf0 = 0, phf1 = 0, phr0 = 0, phr1 = 0;

    int cur = 0;
    for (int t = 0; t < TT; t++) {
        const bool last = (t == TT - 1);

        // xp prefetch (even lanes; latency hidden under the FMA phases)
        float xv0 = 0.0f, xv1 = 0.0f;
        if (kh == 0) { xv0 = xp0[0]; xv1 = xp1[0]; xp0 += HH; xp1 += HH; }

        float2 a0a = {0.f, 0.f}, a0b = {0.f, 0.f};
        float2 a1a = {0.f, 0.f}, a1b = {0.f, 0.f};

        // ---- phase 1: own quarter (local data, __syncthreads-ordered) ----
        {
            const float* p0 = own0 + cur * HROW;
            const float* p1 = own1 + cur * HROW;
#pragma unroll
            for (int ii = 0; ii < 16; ii++) {
                float4 h0 = *(const float4*)(p0 + 4 * ii);
                float4 h1 = *(const float4*)(p1 + 4 * ii);
                float4 w  = wown[ii];
                ffma2(a0a, make_float2(w.x, w.y), make_float2(h0.x, h0.y));
                ffma2(a0b, make_float2(w.z, w.w), make_float2(h0.z, h0.w));
                ffma2(a1a, make_float2(w.x, w.y), make_float2(h1.x, h1.y));
                ffma2(a1b, make_float2(w.z, w.w), make_float2(h1.z, h1.w));
            }
        }

        // ---- peer stores into buffer cur visible? (arrive sent at peer's
        //      previous-step end; propagation overlapped with phase 1) ----
        if (cur == 0) { mbar_wait_cluster(mfull0, phf0); phf0 ^= 1; }
        else          { mbar_wait_cluster(mfull1, phf1); phf1 ^= 1; }

        // ---- phase 2: peer quarter ----
        {
            const float* p0 = pr0 + cur * HROW;
            const float* p1 = pr1 + cur * HROW;
#pragma unroll
            for (int ii = 0; ii < 16; ii++) {
                float4 h0 = *(const float4*)(p0 + 4 * ii);
                float4 h1 = *(const float4*)(p1 + 4 * ii);
                float4 w  = wpeer[ii];
                ffma2(a0a, make_float2(w.x, w.y), make_float2(h0.x, h0.y));
                ffma2(a0b, make_float2(w.z, w.w), make_float2(h0.z, h0.w));
                ffma2(a1a, make_float2(w.x, w.y), make_float2(h1.x, h1.y));
                ffma2(a1b, make_float2(w.z, w.w), make_float2(h1.z, h1.w));
            }
        }

        float s0 = (a0a.x + a0a.y) + (a0b.x + a0b.y);
        float s1 = (a1a.x + a1a.y) + (a1b.x + a1b.y);
        s0 += __shfl_down_sync(0xffffffffu, s0, 1);   // combine kh quarters
        s1 += __shfl_down_sync(0xffffffffu, s1, 1);

        int nxt = cur ^ 1;

        // ---- backpressure: peer finished reading its buffer nxt?
        //      (arrive sent a full step ago -> fast path) ----
        if (nxt == 0) { mbar_wait_cluster(mrdone0, phr0); phr0 ^= 1; }
        else          { mbar_wait_cluster(mrdone1, phr1); phr1 ^= 1; }

        if (kh == 0) {
            float r0 = fmaxf(xv0 + bj + s0, 0.0f);
            float r1 = fmaxf(xv1 + bj + s1, 0.0f);
            // local state
            sm_h0[nxt][slot] = r0;
            sm_h1[nxt][slot] = r1;
            if (!last) {
                // peer state via DSMEM (skipped on last step: no consumer)
                uint32_t off = (uint32_t)(nxt * HROW + slot) * 4u;
                asm volatile("st.shared::cluster.f32 [%0], %1;"
                             :: "r"(rem0 + off), "f"(r0) : "memory");
                asm volatile("st.shared::cluster.f32 [%0], %1;"
                             :: "r"(rem1 + off), "f"(r1) : "memory");
            }
            // global output (consumed by next layer's projection / FC)
            ho0[0] = r0; ho1[0] = r1;
            ho0 += HH;  ho1 += HH;
        }

        // all CTA threads' reads of cur + stores into nxt done / issued
        __syncthreads();
        if (tid == 0 && !last) {
            // cumulative release: orders every thread's DSMEM stores
            mbar_arrive_remote(rmb + 16 + (uint32_t)cur * 8);  // peer.rdone[cur]
            mbar_arrive_remote(rmb + (uint32_t)nxt * 8);       // peer.full[nxt]
        }
        cur = nxt;
    }

    // drain: no CTA exits while any peer-directed traffic could be in flight
    asm volatile("barrier.cluster.arrive.aligned;" ::: "memory");
    asm volatile("barrier.cluster.wait.aligned;"   ::: "memory");
}

// ---------------------------------------------------------------------------
// Final FC: out[b,c] = sum_k h[b,T-1,k]*W_fc[c,k] + b_fc[c]
// ---------------------------------------------------------------------------
__global__ void fc_kernel(const float* __restrict__ Wfc,
                          const float* __restrict__ bfc,
                          float* __restrict__ out) {
    int b   = blockIdx.x;
    int tid = threadIdx.x;
    __shared__ float red[8];
    float hv = g_h[((size_t)b * TT + (TT - 1)) * HH + tid];
#pragma unroll
    for (int c = 0; c < CC; c++) {
        float p = hv * Wfc[(size_t)c * HH + tid];
#pragma unroll
        for (int o = 16; o > 0; o >>= 1)
            p += __shfl_down_sync(0xffffffffu, p, o);
        if ((tid & 31) == 0) red[tid >> 5] = p;
        __syncthreads();
        if (tid == 0) {
            float s = 0.0f;
#pragma unroll
            for (int w = 0; w < 8; w++) s += red[w];
            out[b * CC + c] = s + bfc[c];
        }
        __syncthreads();
    }
}

// ---------------------------------------------------------------------------
extern "C" void kernel_launch(void* const* d_in, const int* in_sizes, int n_in,
                              void* d_out, int out_size) {
    const float* x      = (const float*)d_in[0];
    const float* W_ih0  = (const float*)d_in[1];
    const float* b_ih0  = (const float*)d_in[2];
    const float* W_ih   = (const float*)d_in[3];
    const float* b_ih   = (const float*)d_in[4];
    const float* W_hh   = (const float*)d_in[5];
    const float* b_hh   = (const float*)d_in[6];
    const float* W_fc   = (const float*)d_in[7];
    const float* b_fc   = (const float*)d_in[8];
    float*       out    = (float*)d_out;

    proj0_kernel<<<BB * TT, HH>>>(x, W_ih0, b_ih0);

    for (int l = 0; l < LL; l++) {
        scan_kernel<<<BB, 256>>>(W_hh, b_hh, l);
        if (l < LL - 1)
            proj_kernel<<<dim3((BB * TT) / 128, HH / 128), 256>>>(W_ih, b_ih, l);
    }

    fc_kernel<<<BB, HH>>>(W_fc, b_fc, out);
}

// round 6
// speedup vs baseline: 1.0403x; 1.0403x over previous
#include <cuda_runtime.h>
#include <cstdint>

#define BB 128
#define TT 784
#define HH 256
#define LL 20
#define CC 10

// Scratch (device globals: allocation-free per harness rules)
__device__ float g_xp[(size_t)BB * TT * HH];   // per-layer input projection [B*T, H]
__device__ float g_h [(size_t)BB * TT * HH];   // per-layer hidden output   [B*T, H]

// ---------------------------------------------------------------------------
// helpers
// ---------------------------------------------------------------------------
__device__ __forceinline__ uint32_t smem_u32(const void* p) {
    uint32_t a;
    asm("{ .reg .u64 t; cvta.to.shared.u64 t, %1; cvt.u32.u64 %0, t; }"
        : "=r"(a) : "l"(p));
    return a;
}

// packed fp32x2 fma: c = a*b + c  (two independent rn FMAs per issue)
__device__ __forceinline__ void ffma2(float2& c, float2 a, float2 b) {
    union U { float2 f; unsigned long long u; };
    U A, Bv, C;
    A.f = a; Bv.f = b; C.f = c;
    asm("fma.rn.f32x2 %0, %1, %2, %3;"
        : "=l"(C.u) : "l"(A.u), "l"(Bv.u), "l"(C.u));
    c = C.f;
}

// cluster-scope parity wait on a local mbarrier (acquire: peer DSMEM stores
// become visible)
__device__ __forceinline__ void mbar_wait_cluster(uint32_t mbar, uint32_t parity) {
    uint32_t done;
    asm volatile(
        "{\n\t.reg .pred p;\n\t"
        "mbarrier.try_wait.parity.acquire.cluster.shared::cta.b64 p, [%1], %2;\n\t"
        "selp.b32 %0, 1, 0, p;\n\t}"
        : "=r"(done) : "r"(mbar), "r"(parity) : "memory");
    while (!done) {
        asm volatile(
            "{\n\t.reg .pred p;\n\t"
            "mbarrier.try_wait.parity.acquire.cluster.shared::cta.b64 p, [%1], %2, 0x989680;\n\t"
            "selp.b32 %0, 1, 0, p;\n\t}"
            : "=r"(done) : "r"(mbar), "r"(parity) : "memory");
    }
}

// release.cluster arrive on a REMOTE (peer-CTA) mbarrier (addr pre-mapa'd)
__device__ __forceinline__ void mbar_arrive_remote(uint32_t remote_mbar) {
    asm volatile("mbarrier.arrive.release.cluster.shared::cluster.b64 _, [%0];"
                 :: "r"(remote_mbar) : "memory");
}

// ---------------------------------------------------------------------------
// Layer-0 projection: xp[b,t,h] = x[b,t,0]*W_ih0[h,0] + b_ih0[h]  (I==1)
// ---------------------------------------------------------------------------
__global__ void proj0_kernel(const float* __restrict__ x,
                             const float* __restrict__ W0,
                             const float* __restrict__ b0) {
    int row = blockIdx.x;
    int j   = threadIdx.x;
    g_xp[(size_t)row * HH + j] = x[row] * W0[j] + b0[j];
}

// ---------------------------------------------------------------------------
// Projection GEMM, f32x2 micro-kernel:
//   g_xp[row, n] = sum_k g_h[row, k] * W_ih[l][n, k] + b_ih[l][n]
// Tiles 128x128, K-tile 16, 256 threads, 8 rows x 4 col-pairs per thread.
// ---------------------------------------------------------------------------
__global__ __launch_bounds__(256) void proj_kernel(const float* __restrict__ Wih,
                                                   const float* __restrict__ bih,
                                                   int l) {
    const float* A    = g_h;
    const float* Bw   = Wih + (size_t)l * HH * HH;
    const float* bias = bih + (size_t)l * HH;
    float*       Cout = g_xp;

    int tid = threadIdx.x;
    int tx  = tid & 15;
    int ty  = tid >> 4;
    int r0  = blockIdx.x * 128;
    int c0  = blockIdx.y * 128;

    __shared__ float Ash[128][17];
    __shared__ float Bsh[16][132];

    float2 acc[8][4];
#pragma unroll
    for (int i = 0; i < 8; i++)
#pragma unroll
        for (int jp = 0; jp < 4; jp++) acc[i][jp] = make_float2(0.f, 0.f);

    for (int kt = 0; kt < HH; kt += 16) {
#pragma unroll
        for (int p = 0; p < 8; p++) {
            int f = tid + p * 256;
            int m = f >> 4;
            int k = f & 15;
            Ash[m][k] = A[(size_t)(r0 + m) * HH + kt + k];
        }
#pragma unroll
        for (int p = 0; p < 8; p++) {
            int f = tid + p * 256;
            int n = f >> 4;
            int k = f & 15;
            Bsh[k][n] = Bw[(size_t)(c0 + n) * HH + kt + k];
        }
        __syncthreads();
#pragma unroll
        for (int kk = 0; kk < 16; kk++) {
            float4 bv0 = *(const float4*)&Bsh[kk][tx * 8];
            float4 bv1 = *(const float4*)&Bsh[kk][tx * 8 + 4];
            float2 bp[4] = { {bv0.x, bv0.y}, {bv0.z, bv0.w},
                             {bv1.x, bv1.y}, {bv1.z, bv1.w} };
#pragma unroll
            for (int i = 0; i < 8; i++) {
                float av = Ash[ty * 8 + i][kk];
                float2 aa = {av, av};
#pragma unroll
                for (int jp = 0; jp < 4; jp++)
                    ffma2(acc[i][jp], aa, bp[jp]);
            }
        }
        __syncthreads();
    }

    float bj[8];
#pragma unroll
    for (int j = 0; j < 8; j++) bj[j] = bias[c0 + tx * 8 + j];
#pragma unroll
    for (int i = 0; i < 8; i++) {
        int row = r0 + ty * 8 + i;
#pragma unroll
        for (int jp = 0; jp < 4; jp++) {
            Cout[(size_t)row * HH + c0 + tx * 8 + 2 * jp]     = acc[i][jp].x + bj[2 * jp];
            Cout[(size_t)row * HH + c0 + tx * 8 + 2 * jp + 1] = acc[i][jp].y + bj[2 * jp + 1];
        }
    }
}

// ---------------------------------------------------------------------------
// Recurrent scan, cluster-of-2, 512 threads, W in registers, mbarrier sync.
//
// Grid 128 CTAs (64 clusters of 2), 512 threads. Cluster = 2 batch samples.
// CTA rank r computes output cols [r*128, +128).
// Thread (j = tid>>2, kq = tid&3): owns W row jg = r*128+j over TWO 32-wide
// k-chunks: own  chunk k in [rank*128 + kq*32, +32)  (produced locally)
//           peer chunk k in [peer*128 + kq*32, +32)  (arrives via DSMEM)
// 64 W floats/thread -> ~120 regs -> 16 warps (4/SMSP) for latency hiding.
// Per step: phase1 FMA own chunk; wait full[cur] (peer arrive overlapped);
// phase2 FMA peer chunk; 2-shfl combine of 4 kq partials; kq==0 lanes do
// relu + local/DSMEM/global stores; __syncthreads; tid0 remote-arrives
// peer.full[nxt]. rdone backpressure removed: the full[] chain already
// guarantees peer finished reading buffer nxt (its arrive for step t
// postdates its reads of step t-1). Last step skips DSMEM+arrive; final
// cluster barrier drains (R5-proven termination).
// h chunk stride 40 floats so the 4 kq streams hit disjoint bank groups.
// ---------------------------------------------------------------------------
#define CPAD 40            // floats per 32-col chunk (pad 8 -> +8 banks per kq)
#define SBUF (8 * CPAD)    // floats per (buffer, sample) = 320

__global__ __launch_bounds__(512, 1) __cluster_dims__(2, 1, 1)
void scan_kernel(const float* __restrict__ Whh,
                 const float* __restrict__ bhh,
                 int l) {
    __shared__ __align__(16) float sm_h[2][2][SBUF];     // [buffer][sample][...]
    __shared__ __align__(8)  unsigned long long mb[2];   // full0, full1

    const int tid  = threadIdx.x;
    const int j    = tid >> 2;          // 0..127 local output col
    const int kq   = tid & 3;           // k-chunk selector
    const int rank = blockIdx.x & 1;
    const int peer = rank ^ 1;
    const int pair = blockIdx.x >> 1;   // 0..63
    const int b0   = pair * 2;
    const int b1   = b0 + 1;
    const int jg   = rank * 128 + j;    // global output col

    // ---- load W chunks into registers (once per layer) ----
    float4 wown[8], wpeer[8];
    {
        const float* Wrow = Whh + ((size_t)l * HH + jg) * HH;
        const float4* po = (const float4*)(Wrow + rank * 128 + kq * 32);
        const float4* pp = (const float4*)(Wrow + peer * 128 + kq * 32);
#pragma unroll
        for (int i = 0; i < 8; i++) wown[i]  = po[i];
#pragma unroll
        for (int i = 0; i < 8; i++) wpeer[i] = pp[i];
    }

    // ---- zero h state (both buffers, both samples) ----
    for (int i = tid; i < 2 * 2 * SBUF; i += 512)
        ((float*)sm_h)[i] = 0.0f;

    // ---- mbarrier setup ----
    uint32_t mb_base = smem_u32(&mb[0]);
    __syncthreads();
    if (tid == 0) {
        asm volatile("mbarrier.init.shared.b64 [%0], %1;" :: "r"(mb_base),     "r"(1) : "memory");
        asm volatile("mbarrier.init.shared.b64 [%0], %1;" :: "r"(mb_base + 8), "r"(1) : "memory");
        // pre-arm full[0]: buffer 0 (zeros) is valid
        asm volatile("mbarrier.arrive.shared.b64 _, [%0];" :: "r"(mb_base) : "memory");
    }
    __syncthreads();
    // both CTAs' smem (buffers + barriers) valid before any remote traffic
    asm volatile("barrier.cluster.arrive.aligned;" ::: "memory");
    asm volatile("barrier.cluster.wait.aligned;"   ::: "memory");

    // remote (peer CTA) addresses
    uint32_t loc = smem_u32(&sm_h[0][0][0]);
    uint32_t rem, rmb;
    asm("mapa.shared::cluster.u32 %0, %1, %2;" : "=r"(rem) : "r"(loc), "r"(peer));
    asm("mapa.shared::cluster.u32 %0, %1, %2;" : "=r"(rmb) : "r"(mb_base), "r"(peer));

    // smem read bases: global chunk q of col c lives at q*CPAD + (c&31)
    const float* ownb = &sm_h[0][0][(rank * 4 + kq) * CPAD];
    const float* prb  = &sm_h[0][0][(peer * 4 + kq) * CPAD];

    // kq==0 lane state
    float bj = 0.0f;
    const float* xp0 = g_xp + (size_t)b0 * TT * HH + jg;
    const float* xp1 = g_xp + (size_t)b1 * TT * HH + jg;
    float*       ho0 = g_h  + (size_t)b0 * TT * HH + jg;
    float*       ho1 = g_h  + (size_t)b1 * TT * HH + jg;
    if (kq == 0) bj = bhh[l * HH + jg];

    // write slot for col jg
    const int slot = (jg >> 5) * CPAD + (jg & 31);

    int phf0 = 0, phf1 = 0;
    int cur = 0;
    for (int t = 0; t < TT; t++) {
        const bool last = (t == TT - 1);

        // xp prefetch (kq==0 lanes; latency hidden under the FMA phases)
        float xv0 = 0.0f, xv1 = 0.0f;
        if (kq == 0) { xv0 = xp0[0]; xv1 = xp1[0]; xp0 += HH; xp1 += HH; }

        float2 a0a = {0.f, 0.f}, a0b = {0.f, 0.f};
        float2 a1a = {0.f, 0.f}, a1b = {0.f, 0.f};

        // ---- phase 1: own chunk (local data, __syncthreads-ordered) ----
        {
            const float* p0 = ownb + (cur * 2 + 0) * SBUF;
            const float* p1 = ownb + (cur * 2 + 1) * SBUF;
#pragma unroll
            for (int ii = 0; ii < 8; ii++) {
                float4 h0 = *(const float4*)(p0 + 4 * ii);
                float4 h1 = *(const float4*)(p1 + 4 * ii);
                float4 w  = wown[ii];
                ffma2(a0a, make_float2(w.x, w.y), make_float2(h0.x, h0.y));
                ffma2(a0b, make_float2(w.z, w.w), make_float2(h0.z, h0.w));
                ffma2(a1a, make_float2(w.x, w.y), make_float2(h1.x, h1.y));
                ffma2(a1b, make_float2(w.z, w.w), make_float2(h1.z, h1.w));
            }
        }

        // ---- peer stores into buffer cur visible? (overlapped with phase 1) --
        if (cur == 0) { mbar_wait_cluster(mb_base, phf0); phf0 ^= 1; }
        else          { mbar_wait_cluster(mb_base + 8, phf1); phf1 ^= 1; }

        // ---- phase 2: peer chunk ----
        {
            const float* p0 = prb + (cur * 2 + 0) * SBUF;
            const float* p1 = prb + (cur * 2 + 1) * SBUF;
#pragma unroll
            for (int ii = 0; ii < 8; ii++) {
                float4 h0 = *(const float4*)(p0 + 4 * ii);
                float4 h1 = *(const float4*)(p1 + 4 * ii);
                float4 w  = wpeer[ii];
                ffma2(a0a, make_float2(w.x, w.y), make_float2(h0.x, h0.y));
                ffma2(a0b, make_float2(w.z, w.w), make_float2(h0.z, h0.w));
                ffma2(a1a, make_float2(w.x, w.y), make_float2(h1.x, h1.y));
                ffma2(a1b, make_float2(w.z, w.w), make_float2(h1.z, h1.w));
            }
        }

        float s0 = (a0a.x + a0a.y) + (a0b.x + a0b.y);
        float s1 = (a1a.x + a1a.y) + (a1b.x + a1b.y);
        // combine the 4 kq partials (lanes kq=0..3 adjacent within 4-group)
        s0 += __shfl_down_sync(0xffffffffu, s0, 1);
        s1 += __shfl_down_sync(0xffffffffu, s1, 1);
        s0 += __shfl_down_sync(0xffffffffu, s0, 2);
        s1 += __shfl_down_sync(0xffffffffu, s1, 2);

        int nxt = cur ^ 1;

        if (kq == 0) {
            float r0 = fmaxf(xv0 + bj + s0, 0.0f);
            float r1 = fmaxf(xv1 + bj + s1, 0.0f);
            // local state
            sm_h[nxt][0][slot] = r0;
            sm_h[nxt][1][slot] = r1;
            if (!last) {
                // peer state via DSMEM (skipped on last step: no consumer;
                // in-flight remote traffic at exit caused the R3/R4 ULF)
                uint32_t off0 = (uint32_t)((nxt * 2 + 0) * SBUF + slot) * 4u;
                uint32_t off1 = (uint32_t)((nxt * 2 + 1) * SBUF + slot) * 4u;
                asm volatile("st.shared::cluster.f32 [%0], %1;"
                             :: "r"(rem + off0), "f"(r0) : "memory");
                asm volatile("st.shared::cluster.f32 [%0], %1;"
                             :: "r"(rem + off1), "f"(r1) : "memory");
            }
            // global output (consumed by next layer's projection / FC)
            ho0[0] = r0; ho1[0] = r1;
            ho0 += HH;  ho1 += HH;
        }

        // all threads' reads of cur done + stores into nxt issued
        __syncthreads();
        if (tid == 0 && !last)
            mbar_arrive_remote(rmb + (uint32_t)nxt * 8);   // peer.full[nxt]
        cur = nxt;
    }

    // drain: no CTA exits while any peer-directed traffic could be in flight
    asm volatile("barrier.cluster.arrive.aligned;" ::: "memory");
    asm volatile("barrier.cluster.wait.aligned;"   ::: "memory");
}

// ---------------------------------------------------------------------------
// Final FC: out[b,c] = sum_k h[b,T-1,k]*W_fc[c,k] + b_fc[c]
// ---------------------------------------------------------------------------
__global__ void fc_kernel(const float* __restrict__ Wfc,
                          const float* __restrict__ bfc,
                          float* __restrict__ out) {
    int b   = blockIdx.x;
    int tid = threadIdx.x;
    __shared__ float red[8];
    float hv = g_h[((size_t)b * TT + (TT - 1)) * HH + tid];
#pragma unroll
    for (int c = 0; c < CC; c++) {
        float p = hv * Wfc[(size_t)c * HH + tid];
#pragma unroll
        for (int o = 16; o > 0; o >>= 1)
            p += __shfl_down_sync(0xffffffffu, p, o);
        if ((tid & 31) == 0) red[tid >> 5] = p;
        __syncthreads();
        if (tid == 0) {
            float s = 0.0f;
#pragma unroll
            for (int w = 0; w < 8; w++) s += red[w];
            out[b * CC + c] = s + bfc[c];
        }
        __syncthreads();
    }
}

// ---------------------------------------------------------------------------
extern "C" void kernel_launch(void* const* d_in, const int* in_sizes, int n_in,
                              void* d_out, int out_size) {
    const float* x      = (const float*)d_in[0];
    const float* W_ih0  = (const float*)d_in[1];
    const float* b_ih0  = (const float*)d_in[2];
    const float* W_ih   = (const float*)d_in[3];
    const float* b_ih   = (const float*)d_in[4];
    const float* W_hh   = (const float*)d_in[5];
    const float* b_hh   = (const float*)d_in[6];
    const float* W_fc   = (const float*)d_in[7];
    const float* b_fc   = (const float*)d_in[8];
    float*       out    = (float*)d_out;

    proj0_kernel<<<BB * TT, HH>>>(x, W_ih0, b_ih0);

    for (int l = 0; l < LL; l++) {
        scan_kernel<<<BB, 512>>>(W_hh, b_hh, l);
        if (l < LL - 1)
            proj_kernel<<<dim3((BB * TT) / 128, HH / 128), 256>>>(W_ih, b_ih, l);
    }

    fc_kernel<<<BB, HH>>>(W_fc, b_fc, out);
}